// round 9
// baseline (speedup 1.0000x reference)
#include <cuda_runtime.h>
#include <cuda_bf16.h>
#include <cstdint>

// Problem constants (fixed by the dataset)
#define B 8
#define L 2048
#define H 1024
#define C 64
#define NROWS   (B * L)              // 16384
#define SROWS   16                   // rows per stage (16*4KB = 64KB)
#define STAGE_BYTES (SROWS * H * 4)  // 65536
#define NSTAGES_TOT (NROWS / SROWS)  // 1024
#define NSTAGE  3                    // ring depth (192 KB dynamic smem)
#define GRID    148                  // one persistent block per SM
#define THREADS 512                  // 16 warps: warp-per-row per stage

__device__ float        g_acc[B * C];
__device__ unsigned int g_count;

// ---- PTX helpers -----------------------------------------------------------
static __device__ __forceinline__ uint32_t su32(const void* p) {
    uint32_t a;
    asm("{ .reg .u64 t; cvta.to.shared.u64 t, %1; cvt.u32.u64 %0, t; }"
        : "=r"(a) : "l"(p));
    return a;
}
static __device__ __forceinline__ void mbar_init(uint32_t mbar, uint32_t cnt) {
    asm volatile("mbarrier.init.shared.b64 [%0], %1;" :: "r"(mbar), "r"(cnt) : "memory");
}
static __device__ __forceinline__ void mbar_expect_tx(uint32_t mbar, uint32_t bytes) {
    asm volatile("mbarrier.arrive.expect_tx.shared.b64 _, [%0], %1;"
                 :: "r"(mbar), "r"(bytes) : "memory");
}
static __device__ __forceinline__ void bulk_g2s(uint32_t dst, const void* src,
                                                uint32_t bytes, uint32_t mbar) {
    asm volatile(
        "cp.async.bulk.shared::cta.global.mbarrier::complete_tx::bytes "
        "[%0], [%1], %2, [%3];"
        :: "r"(dst), "l"(src), "r"(bytes), "r"(mbar) : "memory");
}
static __device__ __forceinline__ void mbar_wait(uint32_t mbar, uint32_t parity) {
    asm volatile(
        "{\n\t"
        ".reg .pred P;\n\t"
        "WL_%=:\n\t"
        "mbarrier.try_wait.parity.acquire.cta.shared::cta.b64 P, [%0], %1, 0x989680;\n\t"
        "@P bra.uni WD_%=;\n\t"
        "bra.uni WL_%=;\n\t"
        "WD_%=:\n\t"
        "}"
        :: "r"(mbar), "r"(parity) : "memory");
}

// ---------------------------------------------------------------------------
// R9: persistent per-SM pipeline. cp.async.bulk keeps 2-3 x 64KB stages in
// flight per SM at ALL times (decoupled from warp scheduling / barriers),
// consumers compute from smem. Fence-free atomic flush + last-block finalize.
// ---------------------------------------------------------------------------
__global__ __launch_bounds__(THREADS, 1) void fused_kernel(
    const float* __restrict__ feature,       // [B*L, H]
    const float* __restrict__ fc_weight,     // [H]
    const float* __restrict__ fc_bias,       // [1]
    const int*   __restrict__ position_list, // [B*C*2]
    float* __restrict__ out)                 // [B*C]
{
    extern __shared__ __align__(128) unsigned char dyn[];   // 3 x 64KB stages
    __shared__ float sw[H];                  // weights (4 KB)
    __shared__ float sacc[B * C];            // local span accumulator (2 KB)
    __shared__ float sproj[SROWS];
    __shared__ unsigned long long mbar_s[NSTAGE];
    __shared__ bool  is_last;
    __shared__ int   s_sink;

    const int tid  = threadIdx.x;
    const int blk  = blockIdx.x;
    const int warp = tid >> 5;
    const int lane = tid & 31;

    // Stage weights, zero local accumulator, init barriers
    #pragma unroll
    for (int i = tid; i < H; i += THREADS) sw[i] = fc_weight[i];
    if (tid < B * C) sacc[tid] = 0.0f;
    if (tid == 0) {
        #pragma unroll
        for (int s = 0; s < NSTAGE; s++) mbar_init(su32(&mbar_s[s]), 1u);
    }
    __syncthreads();

    const uint32_t stage0 = su32(dyn);
    // number of stages this block owns: s = blk, blk+GRID, ...
    const int nst = (NSTAGES_TOT - blk + GRID - 1) / GRID;

    // Prologue: fill the ring
    if (tid == 0) {
        const int npre = nst < NSTAGE ? nst : NSTAGE;
        for (int j = 0; j < npre; j++) {
            const int s = blk + j * GRID;
            const uint32_t mb = su32(&mbar_s[j]);
            mbar_expect_tx(mb, STAGE_BYTES);
            bulk_g2s(stage0 + j * STAGE_BYTES,
                     feature + (size_t)s * SROWS * H, STAGE_BYTES, mb);
        }
    }

    const float4* __restrict__ w4 = reinterpret_cast<const float4*>(sw);

    for (int i = 0; i < nst; i++) {
        const int slot = i % NSTAGE;
        const uint32_t ph = (uint32_t)((i / NSTAGE) & 1);
        mbar_wait(su32(&mbar_s[slot]), ph);

        const int s     = blk + i * GRID;
        const int batch = s >> 7;                 // s*16 / 2048
        const int w0    = (s * SROWS) & (L - 1);  // within-batch window start

        // Compute: warp-per-row from smem stage
        const float4* __restrict__ f4 = reinterpret_cast<const float4*>(
            dyn + (size_t)slot * STAGE_BYTES + (size_t)warp * H * 4);
        float4 a4 = make_float4(0.f, 0.f, 0.f, 0.f);
        #pragma unroll
        for (int k = 0; k < 8; k++) {
            const int idx = k * 32 + lane;
            float4 v = f4[idx];
            float4 w = w4[idx];
            a4.x = fmaf(v.x, w.x, a4.x);
            a4.y = fmaf(v.y, w.y, a4.y);
            a4.z = fmaf(v.z, w.z, a4.z);
            a4.w = fmaf(v.w, w.w, a4.w);
        }
        float a = (a4.x + a4.y) + (a4.z + a4.w);
        #pragma unroll
        for (int o = 16; o > 0; o >>= 1)
            a += __shfl_xor_sync(0xFFFFFFFFu, a, o);
        if (lane == 0) sproj[warp] = a;
        __syncthreads();          // all stage reads done, sproj visible

        // Re-arm this slot with the next pending stage (DRAM stays busy)
        if (tid == 0 && i + NSTAGE < nst) {
            const int s2 = blk + (i + NSTAGE) * GRID;
            const uint32_t mb = su32(&mbar_s[slot]);
            mbar_expect_tx(mb, STAGE_BYTES);
            bulk_g2s(stage0 + slot * STAGE_BYTES,
                     feature + (size_t)s2 * SROWS * H, STAGE_BYTES, mb);
        }

        // Scatter 16-row window into local span accumulator (threads 0..63)
        if (tid < C) {
            const int si  = (batch * C + tid) * 2;
            const int src = position_list[si + 0];
            const int end = position_list[si + 1];
            int lo = src - w0; if (lo < 0) lo = 0;
            int hi = end - w0; if (hi > SROWS - 1) hi = SROWS - 1;
            if (lo <= hi) {
                float sum = 0.0f;
                #pragma unroll
                for (int r = 0; r < SROWS; r++)
                    if (r >= lo && r <= hi) sum += sproj[r];
                sacc[batch * C + tid] += sum;
            }
        }
        __syncthreads();          // sproj/sacc safe for next iteration
    }

    // --- Flush local accumulator (value-returning atomics = release) ---
    if (tid < B * C) {
        const float s = sacc[tid];
        if (s != 0.0f) {
            float old = atomicAdd(&g_acc[tid], s);
            if (__float_as_uint(old) == 0xDEADBEEFu) s_sink = 1;
        }
    }
    __syncthreads();

    // --- Arrive; last block finalizes ---
    if (tid == 0) {
        unsigned int prev = atomicAdd(&g_count, 1u);
        is_last = (prev == GRID - 1);
    }
    __syncthreads();

    if (is_last && tid < B * C) {
        const int src = position_list[tid * 2 + 0];
        const int end = position_list[tid * 2 + 1];
        const float v = __ldcg(&g_acc[tid]);
        out[tid] = v / (float)(end - src + 1) + fc_bias[0];
        __stcg(&g_acc[tid], 0.0f);
        if (tid == 0) g_count = 0u;
    }
}

// ---------------------------------------------------------------------------
extern "C" void kernel_launch(void* const* d_in, const int* in_sizes, int n_in,
                              void* d_out, int out_size) {
    const float* feature       = (const float*)d_in[0];  // [B,L,H] f32
    const float* fc_weight     = (const float*)d_in[1];  // [1,H]   f32
    const float* fc_bias       = (const float*)d_in[2];  // [1]     f32
    const int*   position_list = (const int*)  d_in[3];  // [B,C,2] i32
    float* out = (float*)d_out;                          // [B*C,1] f32

    const int dyn_bytes = NSTAGE * STAGE_BYTES;          // 196608
    cudaFuncSetAttribute(fused_kernel,
                         cudaFuncAttributeMaxDynamicSharedMemorySize, dyn_bytes);
    fused_kernel<<<GRID, THREADS, dyn_bytes>>>(feature, fc_weight, fc_bias,
                                               position_list, out);
}

// round 10
// speedup vs baseline: 1.1600x; 1.1600x over previous
#include <cuda_runtime.h>
#include <cuda_bf16.h>

// Problem constants (fixed by the dataset)
#define B 8
#define L 2048
#define H 1024
#define C 64
#define RPP 32                     // rows per pass (4 chunks x 8 warps)
#define NPASS (B * L / RPP)        // 512 passes
#define GRID  444                  // 148 SMs x 3 resident blocks, exact fill

// Persistent scratch (zero-initialized at module load; self-reset each launch)
__device__ float        g_acc[B * C];
__device__ unsigned int g_count;
__device__ unsigned int g_ticket;

// ---------------------------------------------------------------------------
// R10: R5's proven body (statically unrolled 4x8-row chunks, smem weights,
// fence-free atomic scatter) + work-stealing pass scheduler so every SM ends
// at the same time (R5's 4-vs-3 resident-block tail was the ~1.4us loss).
// ---------------------------------------------------------------------------
__global__ __launch_bounds__(256, 3) void fused_kernel(
    const float* __restrict__ feature,       // [B*L, H]
    const float* __restrict__ fc_weight,     // [H]
    const float* __restrict__ fc_bias,       // [1]
    const int*   __restrict__ position_list, // [B*C*2]
    float* __restrict__ out)                 // [B*C]
{
    __shared__ float sw[H];                  // weights (4 KB)
    __shared__ float sproj[RPP];
    __shared__ bool  is_last;
    __shared__ int   s_sink;                 // forces atomic-return consumption
    __shared__ int   s_next;

    const int tid  = threadIdx.x;
    const int warp = tid >> 5;
    const int lane = tid & 31;

    // Stage weights once
    #pragma unroll
    for (int i = tid; i < H; i += 256) sw[i] = fc_weight[i];
    __syncthreads();

    const float4* __restrict__ w4 = reinterpret_cast<const float4*>(sw);

    int p = blockIdx.x;                      // first pass = own id
    while (p < NPASS) {
        const int batch = p >> 6;            // p*32 / 2048
        const int w0    = (p * RPP) & (L - 1);

        // --- Stage 1: 4 chunks of 8 rows, warp-per-row (R5 body) ---
        const size_t base = (size_t)(p * RPP + warp) * H;
        #pragma unroll
        for (int c = 0; c < 4; c++) {
            const float4* __restrict__ f4 = reinterpret_cast<const float4*>(
                feature + base + (size_t)c * 8 * H);
            float4 a4 = make_float4(0.f, 0.f, 0.f, 0.f);
            #pragma unroll
            for (int i = 0; i < 8; i++) {
                const int idx = i * 32 + lane;       // 0..255 float4s
                float4 v = f4[idx];
                float4 w = w4[idx];
                a4.x = fmaf(v.x, w.x, a4.x);
                a4.y = fmaf(v.y, w.y, a4.y);
                a4.z = fmaf(v.z, w.z, a4.z);
                a4.w = fmaf(v.w, w.w, a4.w);
            }
            float a = (a4.x + a4.y) + (a4.z + a4.w);
            #pragma unroll
            for (int o = 16; o > 0; o >>= 1)
                a += __shfl_xor_sync(0xFFFFFFFFu, a, o);
            if (lane == 0) sproj[c * 8 + warp] = a;
        }
        __syncthreads();

        // --- Stage 2: scatter into span accumulators (threads 0..63) ---
        if (tid < C) {
            const int si  = (batch * C + tid) * 2;   // L2-hot
            const int src = position_list[si + 0];
            const int end = position_list[si + 1];
            int lo = src - w0; if (lo < 0) lo = 0;
            int hi = end - w0; if (hi > RPP - 1) hi = RPP - 1;
            if (lo <= hi) {
                float s = 0.0f;
                #pragma unroll
                for (int r = 0; r < RPP; r++)
                    if (r >= lo && r <= hi) s += sproj[r];
                // Value-returning atomic: L2 completion observed before the
                // (never-true) predicate -> release ordering for the final
                // g_count arrival without MEMBAR/CCTL.
                float old = atomicAdd(&g_acc[batch * C + tid], s);
                if (__float_as_uint(old) == 0xDEADBEEFu) s_sink = 1;
            }
        }

        // --- Steal next pass (also serves as sproj-reuse barrier) ---
        if (tid == 0) s_next = (int)(atomicAdd(&g_ticket, 1u) + GRID);
        __syncthreads();
        p = s_next;
    }

    // --- Arrive; last block finalizes ---
    if (tid == 0) {
        unsigned int prev = atomicAdd(&g_count, 1u);
        is_last = (prev == GRID - 1);
    }
    __syncthreads();

    if (is_last) {
        const float bias = fc_bias[0];
        #pragma unroll
        for (int k = 0; k < 2; k++) {
            const int i = tid + k * 256;     // 0..511
            const int src = position_list[i * 2 + 0];
            const int end = position_list[i * 2 + 1];
            const float v = __ldcg(&g_acc[i]);        // L2-coherent read
            out[i] = v / (float)(end - src + 1) + bias;
            __stcg(&g_acc[i], 0.0f);                  // reset for next launch
        }
        if (tid == 0) { g_count = 0u; g_ticket = 0u; }
    }
}

// ---------------------------------------------------------------------------
extern "C" void kernel_launch(void* const* d_in, const int* in_sizes, int n_in,
                              void* d_out, int out_size) {
    const float* feature       = (const float*)d_in[0];  // [B,L,H] f32
    const float* fc_weight     = (const float*)d_in[1];  // [1,H]   f32
    const float* fc_bias       = (const float*)d_in[2];  // [1]     f32
    const int*   position_list = (const int*)  d_in[3];  // [B,C,2] i32
    float* out = (float*)d_out;                          // [B*C,1] f32

    fused_kernel<<<GRID, 256>>>(feature, fc_weight, fc_bias,
                                position_list, out);
}

// round 11
// speedup vs baseline: 1.3528x; 1.1662x over previous
#include <cuda_runtime.h>
#include <cuda_bf16.h>

// Problem constants (fixed by the dataset)
#define B 8
#define L 2048
#define H 1024
#define C 64
#define RPB 16                     // rows per block (2 chunks x 8 warps)
#define GRID (B * L / RPB)         // 1024 blocks -> one wave at occ 7 (1.2% tail)
#define BPB (L / RPB)              // 128 blocks per batch

// Persistent scratch (zero-initialized at module load; self-reset each launch)
__device__ float        g_acc[B * C];
__device__ unsigned int g_count;

// ---------------------------------------------------------------------------
// R11: R5's proven barrier-free body, re-quantized: grid 1024 x RPB 16 with
// forced occupancy 7 -> single wave, 6.92 blocks/SM, ~1.2% straggler excess
// (vs R5's 15.6% at 3.46 blocks/SM). Epilogue identical (fence-free
// value-returning atomic scatter + last-block finalize).
// ---------------------------------------------------------------------------
__global__ __launch_bounds__(256, 7) void fused_kernel(
    const float* __restrict__ feature,       // [B*L, H]
    const float* __restrict__ fc_weight,     // [H]
    const float* __restrict__ fc_bias,       // [1]
    const int*   __restrict__ position_list, // [B*C*2]
    float* __restrict__ out)                 // [B*C]
{
    __shared__ float sw[H];                  // weights (4 KB)
    __shared__ float sproj[RPB];
    __shared__ bool  is_last;
    __shared__ int   s_sink;                 // forces atomic-return consumption

    const int tid   = threadIdx.x;
    const int blk   = blockIdx.x;
    const int batch = blk / BPB;
    const int row0  = (blk % BPB) * RPB;     // within-batch window start
    const int warp  = tid >> 5;
    const int lane  = tid & 31;

    // Stage weights (4 KB) into smem
    #pragma unroll
    for (int i = tid; i < H; i += 256) sw[i] = fc_weight[i];
    __syncthreads();

    const float4* __restrict__ w4 = reinterpret_cast<const float4*>(sw);

    // --- Stage 1: 2 chunks of 8 rows, warp-per-row (R5 inner loop) ---
    const size_t base = (size_t)(batch * L + row0 + warp) * H;
    #pragma unroll
    for (int c = 0; c < 2; c++) {
        const float4* __restrict__ f4 = reinterpret_cast<const float4*>(
            feature + base + (size_t)c * 8 * H);
        float4 a4 = make_float4(0.f, 0.f, 0.f, 0.f);
        #pragma unroll
        for (int i = 0; i < 8; i++) {
            const int idx = i * 32 + lane;   // 0..255 float4s
            float4 v = f4[idx];
            float4 w = w4[idx];
            a4.x = fmaf(v.x, w.x, a4.x);
            a4.y = fmaf(v.y, w.y, a4.y);
            a4.z = fmaf(v.z, w.z, a4.z);
            a4.w = fmaf(v.w, w.w, a4.w);
        }
        float a = (a4.x + a4.y) + (a4.z + a4.w);
        #pragma unroll
        for (int o = 16; o > 0; o >>= 1)
            a += __shfl_xor_sync(0xFFFFFFFFu, a, o);
        if (lane == 0) sproj[c * 8 + warp] = a;
    }
    __syncthreads();

    // --- Stage 2: scatter into span accumulators (threads 0..63) ---
    if (tid < C) {
        const int si  = (batch * C + tid) * 2;       // L2-hot
        const int src = position_list[si + 0];
        const int end = position_list[si + 1];
        int lo = src - row0; if (lo < 0) lo = 0;
        int hi = end - row0; if (hi > RPB - 1) hi = RPB - 1;
        if (lo <= hi) {
            float s = 0.0f;
            #pragma unroll
            for (int r = 0; r < RPB; r++)
                if (r >= lo && r <= hi) s += sproj[r];
            // Value-returning atomic: L2 completion observed before the
            // (never-true) predicate -> release ordering for the g_count
            // arrival without MEMBAR/CCTL.
            float old = atomicAdd(&g_acc[batch * C + tid], s);
            if (__float_as_uint(old) == 0xDEADBEEFu) s_sink = 1;
        }
    }
    __syncthreads();   // all scatter atomics of this block have completed

    // --- Stage 3: arrive; last block finalizes ---
    if (tid == 0) {
        unsigned int prev = atomicAdd(&g_count, 1u);
        is_last = (prev == GRID - 1);
    }
    __syncthreads();

    if (is_last) {
        const float bias = fc_bias[0];
        #pragma unroll
        for (int k = 0; k < 2; k++) {
            const int i = tid + k * 256;     // 0..511
            const int src = position_list[i * 2 + 0];
            const int end = position_list[i * 2 + 1];
            const float v = __ldcg(&g_acc[i]);        // L2-coherent read
            out[i] = v / (float)(end - src + 1) + bias;
            __stcg(&g_acc[i], 0.0f);                  // reset for next launch
        }
        if (tid == 0) g_count = 0u;
    }
}

// ---------------------------------------------------------------------------
extern "C" void kernel_launch(void* const* d_in, const int* in_sizes, int n_in,
                              void* d_out, int out_size) {
    const float* feature       = (const float*)d_in[0];  // [B,L,H] f32
    const float* fc_weight     = (const float*)d_in[1];  // [1,H]   f32
    const float* fc_bias       = (const float*)d_in[2];  // [1]     f32
    const int*   position_list = (const int*)  d_in[3];  // [B,C,2] i32
    float* out = (float*)d_out;                          // [B*C,1] f32

    fused_kernel<<<GRID, 256>>>(feature, fc_weight, fc_bias,
                                position_list, out);
}